// round 5
// baseline (speedup 1.0000x reference)
#include <cuda_runtime.h>
#include <cstdint>

#define N_NODES 100000
#define N_EDGES 1600000
#define CH      128
#define EDIM    16
#define NB      391      // ceil(N_NODES/256)

// ---------------- scratch (static device globals: no allocation) ----------------
__device__ float g_nodeproj[(size_t)N_NODES * CH];
__device__ float g_agg     [(size_t)N_NODES * CH];
__device__ float g_h       [(size_t)N_NODES * CH];
__device__ int   g_cnt     [N_NODES];
__device__ int   g_off     [N_NODES];
__device__ int   g_cursor  [N_NODES];
__device__ int   g_part    [512];
__device__ int   g_src_sorted[N_EDGES];
__device__ float g_ea_sorted[(size_t)N_EDGES * EDIM];
__device__ int   g_is64;

// ---------------- packed f32x2 helpers (sm_103a) ----------------
static __device__ __forceinline__ unsigned long long pack2(float x, float y) {
    unsigned long long r;
    asm("mov.b64 %0, {%1, %2};" : "=l"(r) : "f"(x), "f"(y));
    return r;
}
static __device__ __forceinline__ void unpack2(unsigned long long v, float &x, float &y) {
    asm("mov.b64 {%0, %1}, %2;" : "=f"(x), "=f"(y) : "l"(v));
}
static __device__ __forceinline__ void ffma2(unsigned long long &d,
                                             unsigned long long a,
                                             unsigned long long b) {
    asm("fma.rn.f32x2 %0, %1, %2, %0;" : "+l"(d) : "l"(a), "l"(b));
}

// ---------------- init: zero counts + dtype sniff (int32 vs int64) -------------
__global__ void init_kernel(const unsigned* __restrict__ p) {
    int i = blockIdx.x * 256 + threadIdx.x;
    if (i < N_NODES) g_cnt[i] = 0;
    if (blockIdx.x == 0) {
        __shared__ int nz;
        if (threadIdx.x == 0) nz = 0;
        __syncthreads();
        if (p[threadIdx.x * 2 + 1] != 0u) atomicAdd(&nz, 1);
        __syncthreads();
        if (threadIdx.x == 0) g_is64 = (nz == 0) ? 1 : 0;
    }
}

static __device__ __forceinline__ int load_eidx(const void* eidx, long long i, int is64) {
    return is64 ? (int)((const long long*)eidx)[i] : ((const int*)eidx)[i];
}

__global__ void count_kernel(const void* __restrict__ eidx) {
    long long t = (long long)blockIdx.x * blockDim.x + threadIdx.x;
    if (t >= N_EDGES) return;
    int dst = load_eidx(eidx, (long long)N_EDGES + t, g_is64);
    atomicAdd(&g_cnt[dst], 1);
}

// ---------------- parallel 3-phase exclusive scan of g_cnt ----------------------
__global__ __launch_bounds__(256) void reduce_kernel() {
    int i = blockIdx.x * 256 + threadIdx.x;
    int x = (i < N_NODES) ? g_cnt[i] : 0;
    __shared__ int ws[8];
    int lane = threadIdx.x & 31, wid = threadIdx.x >> 5;
#pragma unroll
    for (int o = 16; o; o >>= 1) x += __shfl_down_sync(0xffffffffu, x, o);
    if (lane == 0) ws[wid] = x;
    __syncthreads();
    if (wid == 0) {
        int v = (lane < 8) ? ws[lane] : 0;
#pragma unroll
        for (int o = 4; o; o >>= 1) v += __shfl_down_sync(0xffffffffu, v, o);
        if (lane == 0) g_part[blockIdx.x] = v;
    }
}

__global__ __launch_bounds__(512) void scanp_kernel() {
    int tid = threadIdx.x, lane = tid & 31, wid = tid >> 5;
    int v = (tid < NB) ? g_part[tid] : 0;
    int x = v;
#pragma unroll
    for (int o = 1; o < 32; o <<= 1) {
        int y = __shfl_up_sync(0xffffffffu, x, o);
        if (lane >= o) x += y;
    }
    __shared__ int ws[16];
    if (lane == 31) ws[wid] = x;
    __syncthreads();
    if (wid == 0) {
        int t = (lane < 16) ? ws[lane] : 0;
#pragma unroll
        for (int o = 1; o < 16; o <<= 1) {
            int y = __shfl_up_sync(0xffffffffu, t, o);
            if (lane >= o) t += y;
        }
        if (lane < 16) ws[lane] = t;
    }
    __syncthreads();
    int pre = wid ? ws[wid - 1] : 0;
    if (tid < NB) g_part[tid] = pre + x - v;   // exclusive
}

__global__ __launch_bounds__(256) void expand_kernel() {
    int i = blockIdx.x * 256 + threadIdx.x;
    int v = (i < N_NODES) ? g_cnt[i] : 0;
    int lane = threadIdx.x & 31, wid = threadIdx.x >> 5;
    int x = v;
#pragma unroll
    for (int o = 1; o < 32; o <<= 1) {
        int y = __shfl_up_sync(0xffffffffu, x, o);
        if (lane >= o) x += y;
    }
    __shared__ int ws[8];
    if (lane == 31) ws[wid] = x;
    __syncthreads();
    if (wid == 0) {
        int t = (lane < 8) ? ws[lane] : 0;
#pragma unroll
        for (int o = 1; o < 8; o <<= 1) {
            int y = __shfl_up_sync(0xffffffffu, t, o);
            if (lane >= o) t += y;
        }
        if (lane < 8) ws[lane] = t;
    }
    __syncthreads();
    int excl = (wid ? ws[wid - 1] : 0) + x - v + g_part[blockIdx.x];
    if (i < N_NODES) { g_off[i] = excl; g_cursor[i] = excl; }
}

// scatter edges into dst-sorted order
__global__ void scatter_kernel(const void* __restrict__ eidx,
                               const float* __restrict__ edge_attr) {
    long long t = (long long)blockIdx.x * blockDim.x + threadIdx.x;
    if (t >= N_EDGES) return;
    const int is64 = g_is64;
    int src = load_eidx(eidx, t, is64);
    int dst = load_eidx(eidx, (long long)N_EDGES + t, is64);
    int pos = atomicAdd(&g_cursor[dst], 1);
    g_src_sorted[pos] = src;
    const float4* s = reinterpret_cast<const float4*>(&edge_attr[t * EDIM]);
    float4* d = reinterpret_cast<float4*>(&g_ea_sorted[(size_t)pos * EDIM]);
    d[0] = s[0]; d[1] = s[1]; d[2] = s[2]; d[3] = s[3];
}

// ---------------- double-buffered tiled GEMM ------------------------------------
template<int KTOT>
static __device__ __forceinline__ float4 loadA_elem(const float* __restrict__ A0,
                                                    const float* __restrict__ A1,
                                                    int grow, int kb, int k4) {
    float4 v = make_float4(0.f, 0.f, 0.f, 0.f);
    if (grow < N_NODES) {
        const float* base = (KTOT == 128 || kb < 128)
            ? &A0[(size_t)grow * 128 + kb + k4]
            : &A1[(size_t)grow * 128 + (kb - 128) + k4];
        v = *reinterpret_cast<const float4*>(base);
    }
    return v;
}

static __device__ __forceinline__ void stsA(float* As, int m, int k4, float4 v) {
    As[(k4 + 0) * 128 + m] = v.x;
    As[(k4 + 1) * 128 + m] = v.y;
    As[(k4 + 2) * 128 + m] = v.z;
    As[(k4 + 3) * 128 + m] = v.w;
}

static __device__ __forceinline__ void gemm_compute(const float* __restrict__ As,
                                                    const float* __restrict__ Bs,
                                                    unsigned long long acc[8][4],
                                                    int tx, int ty) {
#pragma unroll
    for (int k = 0; k < 16; k++) {
        float4 a0 = *reinterpret_cast<const float4*>(&As[k * 128 + ty * 8]);
        float4 a1 = *reinterpret_cast<const float4*>(&As[k * 128 + ty * 8 + 4]);
        ulonglong2 bb0 = *reinterpret_cast<const ulonglong2*>(&Bs[k * 128 + tx * 8]);
        ulonglong2 bb1 = *reinterpret_cast<const ulonglong2*>(&Bs[k * 128 + tx * 8 + 4]);
        float av[8] = {a0.x, a0.y, a0.z, a0.w, a1.x, a1.y, a1.z, a1.w};
        unsigned long long bv[4] = {bb0.x, bb0.y, bb1.x, bb1.y};
#pragma unroll
        for (int i = 0; i < 8; i++) {
            unsigned long long a2 = pack2(av[i], av[i]);
#pragma unroll
            for (int j = 0; j < 4; j++) ffma2(acc[i][j], a2, bv[j]);
        }
    }
}

template<int KTOT, bool NORM, bool RELU>
__global__ __launch_bounds__(256)
void gemm_kernel(const float* __restrict__ A0, const float* __restrict__ A1,
                 const float* __restrict__ B,
                 const float* __restrict__ bias1, const float* __restrict__ bias2,
                 float* __restrict__ out)
{
    __shared__ float As[2][16 * 128];
    __shared__ float Bs[2][16 * 128];
    const int tid = threadIdx.x;
    const int tx = tid & 15, ty = tid >> 4;
    const int row0 = blockIdx.x * 128;
    const int mA = tid >> 2, k4 = (tid & 3) << 2;
    const int kB = tid >> 5, n4 = tid & 31;

    unsigned long long acc[8][4];
#pragma unroll
    for (int i = 0; i < 8; i++)
#pragma unroll
        for (int j = 0; j < 4; j++) acc[i][j] = 0ull;

    float4 ra0 = loadA_elem<KTOT>(A0, A1, row0 + mA, 0, k4);
    float4 ra1 = loadA_elem<KTOT>(A0, A1, row0 + mA + 64, 0, k4);
    float4 rb0 = reinterpret_cast<const float4*>(&B[(size_t)kB * 128])[n4];
    float4 rb1 = reinterpret_cast<const float4*>(&B[(size_t)(kB + 8) * 128])[n4];
    stsA(As[0], mA, k4, ra0);
    stsA(As[0], mA + 64, k4, ra1);
    reinterpret_cast<float4*>(&Bs[0][kB * 128])[n4] = rb0;
    reinterpret_cast<float4*>(&Bs[0][(kB + 8) * 128])[n4] = rb1;
    __syncthreads();

    int buf = 0;
    for (int kb = 16; kb < KTOT; kb += 16) {
        ra0 = loadA_elem<KTOT>(A0, A1, row0 + mA, kb, k4);
        ra1 = loadA_elem<KTOT>(A0, A1, row0 + mA + 64, kb, k4);
        rb0 = reinterpret_cast<const float4*>(&B[(size_t)(kb + kB) * 128])[n4];
        rb1 = reinterpret_cast<const float4*>(&B[(size_t)(kb + kB + 8) * 128])[n4];
        gemm_compute(As[buf], Bs[buf], acc, tx, ty);
        stsA(As[buf ^ 1], mA, k4, ra0);
        stsA(As[buf ^ 1], mA + 64, k4, ra1);
        reinterpret_cast<float4*>(&Bs[buf ^ 1][kB * 128])[n4] = rb0;
        reinterpret_cast<float4*>(&Bs[buf ^ 1][(kB + 8) * 128])[n4] = rb1;
        __syncthreads();
        buf ^= 1;
    }
    gemm_compute(As[buf], Bs[buf], acc, tx, ty);

    // epilogue
    float vals[8][8];
#pragma unroll
    for (int i = 0; i < 8; i++)
#pragma unroll
        for (int j = 0; j < 4; j++)
            unpack2(acc[i][j], vals[i][2 * j], vals[i][2 * j + 1]);

#pragma unroll
    for (int j = 0; j < 8; j++) {
        float b = bias1[tx * 8 + j];
#pragma unroll
        for (int i = 0; i < 8; i++) vals[i][j] += b;
    }

    float rn[8];
    if (NORM) {
        __syncthreads();
        float* ss = As[0];
        if (tid < 128) ss[tid] = 0.f;
        __syncthreads();
#pragma unroll
        for (int i = 0; i < 8; i++) {
            float p = 0.f;
#pragma unroll
            for (int j = 0; j < 8; j++) p += vals[i][j] * vals[i][j];
            atomicAdd(&ss[ty * 8 + i], p);
        }
        __syncthreads();
        if (tid < 128) {
            float s = ss[tid];
            Bs[0][tid] = 1.0f / fmaxf(sqrtf(s), 1e-12f);
        }
        __syncthreads();
#pragma unroll
        for (int i = 0; i < 8; i++) rn[i] = Bs[0][ty * 8 + i];
    }

#pragma unroll
    for (int i = 0; i < 8; i++) {
        int grow = row0 + ty * 8 + i;
        if (grow < N_NODES) {
            float o[8];
#pragma unroll
            for (int j = 0; j < 8; j++) {
                float v = vals[i][j];
                if (NORM) v = v * rn[i] + bias2[tx * 8 + j];
                if (RELU) v = fmaxf(v, 0.f);
                o[j] = v;
            }
            float4* dst = reinterpret_cast<float4*>(&out[(size_t)grow * 128 + tx * 8]);
            dst[0] = make_float4(o[0], o[1], o[2], o[3]);
            dst[1] = make_float4(o[4], o[5], o[6], o[7]);
        }
    }
}

// ---------------- warp-per-node aggregate: no ea shuffles, uniform LDG broadcast -
// agg[n] = mean_e relu(nodeproj[src(e)] + ea(e) @ We)
// Each lane owns 4 output channels; ea values come from uniform-address LDG.128
// (L1 broadcast, N=1) instead of 32 SHFLs per pair.
__global__ __launch_bounds__(256)
void agg_kernel(const float* __restrict__ nodeproj,
                const float* __restrict__ We,   // [16][128] row-major
                float* __restrict__ agg)
{
    const int lane = threadIdx.x & 31;
    const int warp = threadIdx.x >> 5;

    ulonglong2 w[16];
#pragma unroll
    for (int k = 0; k < 16; k++)
        w[k] = reinterpret_cast<const ulonglong2*>(We)[k * 32 + lane];

    const int n = blockIdx.x * 8 + warp;
    if (n >= N_NODES) return;
    const int beg = g_off[n];
    const int cnt = g_cnt[n];
    const float4* np4 = reinterpret_cast<const float4*>(nodeproj);
    const float4* ea4 = reinterpret_cast<const float4*>(g_ea_sorted);

    float s0 = 0.f, s1 = 0.f, s2 = 0.f, s3 = 0.f;

    for (int c = 0; c < cnt; c += 32) {
        const int nc = min(32, cnt - c);
        // one coalesced load fetches up to 32 src ids for this chunk
        int srcs = (c + lane < cnt) ? g_src_sorted[beg + c + lane] : 0;

        int i = 0;
        for (; i + 2 <= nc; i += 2) {
            const long long e = (long long)beg + c + i;
            const int src0 = __shfl_sync(0xffffffffu, srcs, i);
            const int src1 = __shfl_sync(0xffffffffu, srcs, i + 1);

            float4 a4 = np4[(size_t)src0 * 32 + lane];
            float4 b4 = np4[(size_t)src1 * 32 + lane];
            unsigned long long p0 = pack2(a4.x, a4.y), p1 = pack2(a4.z, a4.w);
            unsigned long long q0 = pack2(b4.x, b4.y), q1 = pack2(b4.z, b4.w);

            const float4* eaA = &ea4[e * 4];        // edge i   : 4 float4
            const float4* eaB = &ea4[(e + 1) * 4];  // edge i+1 : 4 float4
#pragma unroll
            for (int kk = 0; kk < 4; kk++) {
                float4 fa = eaA[kk];   // uniform across warp -> broadcast
                float4 fb = eaB[kk];
                {
                    unsigned long long t = pack2(fa.x, fa.x);
                    ffma2(p0, t, w[kk*4+0].x); ffma2(p1, t, w[kk*4+0].y);
                    t = pack2(fa.y, fa.y);
                    ffma2(p0, t, w[kk*4+1].x); ffma2(p1, t, w[kk*4+1].y);
                    t = pack2(fa.z, fa.z);
                    ffma2(p0, t, w[kk*4+2].x); ffma2(p1, t, w[kk*4+2].y);
                    t = pack2(fa.w, fa.w);
                    ffma2(p0, t, w[kk*4+3].x); ffma2(p1, t, w[kk*4+3].y);
                }
                {
                    unsigned long long t = pack2(fb.x, fb.x);
                    ffma2(q0, t, w[kk*4+0].x); ffma2(q1, t, w[kk*4+0].y);
                    t = pack2(fb.y, fb.y);
                    ffma2(q0, t, w[kk*4+1].x); ffma2(q1, t, w[kk*4+1].y);
                    t = pack2(fb.z, fb.z);
                    ffma2(q0, t, w[kk*4+2].x); ffma2(q1, t, w[kk*4+2].y);
                    t = pack2(fb.w, fb.w);
                    ffma2(q0, t, w[kk*4+3].x); ffma2(q1, t, w[kk*4+3].y);
                }
            }
            float r0, r1, r2, r3, t0, t1, t2, t3;
            unpack2(p0, r0, r1); unpack2(p1, r2, r3);
            unpack2(q0, t0, t1); unpack2(q1, t2, t3);
            s0 += fmaxf(r0, 0.f) + fmaxf(t0, 0.f);
            s1 += fmaxf(r1, 0.f) + fmaxf(t1, 0.f);
            s2 += fmaxf(r2, 0.f) + fmaxf(t2, 0.f);
            s3 += fmaxf(r3, 0.f) + fmaxf(t3, 0.f);
        }
        if (i < nc) {
            const long long e = (long long)beg + c + i;
            const int src = __shfl_sync(0xffffffffu, srcs, i);
            float4 a4 = np4[(size_t)src * 32 + lane];
            unsigned long long p0 = pack2(a4.x, a4.y), p1 = pack2(a4.z, a4.w);
            const float4* eaA = &ea4[e * 4];
#pragma unroll
            for (int kk = 0; kk < 4; kk++) {
                float4 fa = eaA[kk];
                unsigned long long t = pack2(fa.x, fa.x);
                ffma2(p0, t, w[kk*4+0].x); ffma2(p1, t, w[kk*4+0].y);
                t = pack2(fa.y, fa.y);
                ffma2(p0, t, w[kk*4+1].x); ffma2(p1, t, w[kk*4+1].y);
                t = pack2(fa.z, fa.z);
                ffma2(p0, t, w[kk*4+2].x); ffma2(p1, t, w[kk*4+2].y);
                t = pack2(fa.w, fa.w);
                ffma2(p0, t, w[kk*4+3].x); ffma2(p1, t, w[kk*4+3].y);
            }
            float r0, r1, r2, r3;
            unpack2(p0, r0, r1); unpack2(p1, r2, r3);
            s0 += fmaxf(r0, 0.f);
            s1 += fmaxf(r1, 0.f);
            s2 += fmaxf(r2, 0.f);
            s3 += fmaxf(r3, 0.f);
        }
    }

    const float sc = 1.0f / (float)(cnt > 1 ? cnt : 1);
    reinterpret_cast<float4*>(agg)[(size_t)n * 32 + lane] =
        make_float4(s0 * sc, s1 * sc, s2 * sc, s3 * sc);
}

// ---------------- launch -------------------------------------------------------
extern "C" void kernel_launch(void* const* d_in, const int* in_sizes, int n_in,
                              void* d_out, int out_size)
{
    const float* x         = (const float*)d_in[0];
    const void*  edge_idx  = d_in[1];
    const float* edge_attr = (const float*)d_in[2];
    const float* w_msg1    = (const float*)d_in[3];
    const float* b_msg1    = (const float*)d_in[4];
    const float* w_upd1    = (const float*)d_in[5];
    const float* b_upd1    = (const float*)d_in[6];
    const float* bias1     = (const float*)d_in[7];
    const float* w_msg2    = (const float*)d_in[8];
    const float* b_msg2    = (const float*)d_in[9];
    const float* w_upd2    = (const float*)d_in[10];
    const float* b_upd2    = (const float*)d_in[11];
    const float* bias2     = (const float*)d_in[12];
    float* out = (float*)d_out;

    float *np, *ag, *h;
    cudaGetSymbolAddress((void**)&np, g_nodeproj);
    cudaGetSymbolAddress((void**)&ag, g_agg);
    cudaGetSymbolAddress((void**)&h,  g_h);

    const int GEMM_BLOCKS = (N_NODES + 127) / 128;     // 782
    const int CNT_BLOCKS  = (N_EDGES + 255) / 256;
    const int AGG_BLOCKS  = (N_NODES + 7) / 8;         // 12500

    init_kernel<<<NB, 256>>>((const unsigned*)edge_idx);        // 0
    count_kernel<<<CNT_BLOCKS, 256>>>(edge_idx);                // 1
    reduce_kernel<<<NB, 256>>>();                               // 2
    gemm_kernel<128, false, false><<<GEMM_BLOCKS, 256>>>(       // 3 ← ncu profiles this
        x, nullptr, w_msg1, b_msg1, nullptr, np);
    scanp_kernel<<<1, 512>>>();                                 // 4
    expand_kernel<<<NB, 256>>>();                               // 5
    scatter_kernel<<<CNT_BLOCKS, 256>>>(edge_idx, edge_attr);   // 6

    // ---- layer 1 (nodeproj computed at launch 3) ----
    agg_kernel<<<AGG_BLOCKS, 256>>>(np, w_msg1 + 128 * 128, ag);          // 7
    gemm_kernel<256, true, true><<<GEMM_BLOCKS, 256>>>(                   // 8
        x, ag, w_upd1, b_upd1, bias1, h);

    // ---- layer 2 ----
    gemm_kernel<128, false, false><<<GEMM_BLOCKS, 256>>>(                 // 9
        h, nullptr, w_msg2, b_msg2, nullptr, np);
    agg_kernel<<<AGG_BLOCKS, 256>>>(np, w_msg2 + 128 * 128, ag);          // 10
    gemm_kernel<256, true, false><<<GEMM_BLOCKS, 256>>>(                  // 11
        h, ag, w_upd2, b_upd2, bias2, out);

    (void)in_sizes; (void)n_in; (void)out_size;
}

// round 6
// speedup vs baseline: 1.0424x; 1.0424x over previous
#include <cuda_runtime.h>
#include <cstdint>

#define N_NODES 100000
#define N_EDGES 1600000
#define CH      128
#define EDIM    16
#define NB      391      // ceil(N_NODES/256)

// ---------------- scratch (static device globals: no allocation) ----------------
__device__ float g_nodeproj[(size_t)N_NODES * CH];
__device__ float g_agg     [(size_t)N_NODES * CH];
__device__ float g_h       [(size_t)N_NODES * CH];
__device__ int   g_cnt     [N_NODES];
__device__ int   g_off     [N_NODES];
__device__ int   g_cursor  [N_NODES];
__device__ int   g_part    [512];
__device__ int   g_src_sorted[N_EDGES];
__device__ float g_ea_sorted[(size_t)N_EDGES * EDIM];
__device__ int   g_is64;

// ---------------- packed f32x2 helpers (sm_103a) ----------------
static __device__ __forceinline__ unsigned long long pack2(float x, float y) {
    unsigned long long r;
    asm("mov.b64 %0, {%1, %2};" : "=l"(r) : "f"(x), "f"(y));
    return r;
}
static __device__ __forceinline__ void unpack2(unsigned long long v, float &x, float &y) {
    asm("mov.b64 {%0, %1}, %2;" : "=f"(x), "=f"(y) : "l"(v));
}
static __device__ __forceinline__ void ffma2(unsigned long long &d,
                                             unsigned long long a,
                                             unsigned long long b) {
    asm("fma.rn.f32x2 %0, %1, %2, %0;" : "+l"(d) : "l"(a), "l"(b));
}

// ---------------- init: zero counts + dtype sniff (int32 vs int64) -------------
__global__ void init_kernel(const unsigned* __restrict__ p) {
    int i = blockIdx.x * 256 + threadIdx.x;
    if (i < N_NODES) g_cnt[i] = 0;
    if (blockIdx.x == 0) {
        __shared__ int nz;
        if (threadIdx.x == 0) nz = 0;
        __syncthreads();
        if (p[threadIdx.x * 2 + 1] != 0u) atomicAdd(&nz, 1);
        __syncthreads();
        if (threadIdx.x == 0) g_is64 = (nz == 0) ? 1 : 0;
    }
}

static __device__ __forceinline__ int load_eidx(const void* eidx, long long i, int is64) {
    return is64 ? (int)((const long long*)eidx)[i] : ((const int*)eidx)[i];
}

__global__ void count_kernel(const void* __restrict__ eidx) {
    long long t = (long long)blockIdx.x * blockDim.x + threadIdx.x;
    if (t >= N_EDGES) return;
    int dst = load_eidx(eidx, (long long)N_EDGES + t, g_is64);
    atomicAdd(&g_cnt[dst], 1);
}

// ---------------- parallel 3-phase exclusive scan of g_cnt ----------------------
__global__ __launch_bounds__(256) void reduce_kernel() {
    int i = blockIdx.x * 256 + threadIdx.x;
    int x = (i < N_NODES) ? g_cnt[i] : 0;
    __shared__ int ws[8];
    int lane = threadIdx.x & 31, wid = threadIdx.x >> 5;
#pragma unroll
    for (int o = 16; o; o >>= 1) x += __shfl_down_sync(0xffffffffu, x, o);
    if (lane == 0) ws[wid] = x;
    __syncthreads();
    if (wid == 0) {
        int v = (lane < 8) ? ws[lane] : 0;
#pragma unroll
        for (int o = 4; o; o >>= 1) v += __shfl_down_sync(0xffffffffu, v, o);
        if (lane == 0) g_part[blockIdx.x] = v;
    }
}

__global__ __launch_bounds__(512) void scanp_kernel() {
    int tid = threadIdx.x, lane = tid & 31, wid = tid >> 5;
    int v = (tid < NB) ? g_part[tid] : 0;
    int x = v;
#pragma unroll
    for (int o = 1; o < 32; o <<= 1) {
        int y = __shfl_up_sync(0xffffffffu, x, o);
        if (lane >= o) x += y;
    }
    __shared__ int ws[16];
    if (lane == 31) ws[wid] = x;
    __syncthreads();
    if (wid == 0) {
        int t = (lane < 16) ? ws[lane] : 0;
#pragma unroll
        for (int o = 1; o < 16; o <<= 1) {
            int y = __shfl_up_sync(0xffffffffu, t, o);
            if (lane >= o) t += y;
        }
        if (lane < 16) ws[lane] = t;
    }
    __syncthreads();
    int pre = wid ? ws[wid - 1] : 0;
    if (tid < NB) g_part[tid] = pre + x - v;   // exclusive
}

__global__ __launch_bounds__(256) void expand_kernel() {
    int i = blockIdx.x * 256 + threadIdx.x;
    int v = (i < N_NODES) ? g_cnt[i] : 0;
    int lane = threadIdx.x & 31, wid = threadIdx.x >> 5;
    int x = v;
#pragma unroll
    for (int o = 1; o < 32; o <<= 1) {
        int y = __shfl_up_sync(0xffffffffu, x, o);
        if (lane >= o) x += y;
    }
    __shared__ int ws[8];
    if (lane == 31) ws[wid] = x;
    __syncthreads();
    if (wid == 0) {
        int t = (lane < 8) ? ws[lane] : 0;
#pragma unroll
        for (int o = 1; o < 8; o <<= 1) {
            int y = __shfl_up_sync(0xffffffffu, t, o);
            if (lane >= o) t += y;
        }
        if (lane < 8) ws[lane] = t;
    }
    __syncthreads();
    int excl = (wid ? ws[wid - 1] : 0) + x - v + g_part[blockIdx.x];
    if (i < N_NODES) { g_off[i] = excl; g_cursor[i] = excl; }
}

// scatter edges into dst-sorted order
__global__ void scatter_kernel(const void* __restrict__ eidx,
                               const float* __restrict__ edge_attr) {
    long long t = (long long)blockIdx.x * blockDim.x + threadIdx.x;
    if (t >= N_EDGES) return;
    const int is64 = g_is64;
    int src = load_eidx(eidx, t, is64);
    int dst = load_eidx(eidx, (long long)N_EDGES + t, is64);
    int pos = atomicAdd(&g_cursor[dst], 1);
    g_src_sorted[pos] = src;
    const float4* s = reinterpret_cast<const float4*>(&edge_attr[t * EDIM]);
    float4* d = reinterpret_cast<float4*>(&g_ea_sorted[(size_t)pos * EDIM]);
    d[0] = s[0]; d[1] = s[1]; d[2] = s[2]; d[3] = s[3];
}

// ---------------- double-buffered tiled GEMM ------------------------------------
template<int KTOT>
static __device__ __forceinline__ float4 loadA_elem(const float* __restrict__ A0,
                                                    const float* __restrict__ A1,
                                                    int grow, int kb, int k4) {
    float4 v = make_float4(0.f, 0.f, 0.f, 0.f);
    if (grow < N_NODES) {
        const float* base = (KTOT == 128 || kb < 128)
            ? &A0[(size_t)grow * 128 + kb + k4]
            : &A1[(size_t)grow * 128 + (kb - 128) + k4];
        v = *reinterpret_cast<const float4*>(base);
    }
    return v;
}

static __device__ __forceinline__ void stsA(float* As, int m, int k4, float4 v) {
    As[(k4 + 0) * 128 + m] = v.x;
    As[(k4 + 1) * 128 + m] = v.y;
    As[(k4 + 2) * 128 + m] = v.z;
    As[(k4 + 3) * 128 + m] = v.w;
}

static __device__ __forceinline__ void gemm_compute(const float* __restrict__ As,
                                                    const float* __restrict__ Bs,
                                                    unsigned long long acc[8][4],
                                                    int tx, int ty) {
#pragma unroll
    for (int k = 0; k < 16; k++) {
        float4 a0 = *reinterpret_cast<const float4*>(&As[k * 128 + ty * 8]);
        float4 a1 = *reinterpret_cast<const float4*>(&As[k * 128 + ty * 8 + 4]);
        ulonglong2 bb0 = *reinterpret_cast<const ulonglong2*>(&Bs[k * 128 + tx * 8]);
        ulonglong2 bb1 = *reinterpret_cast<const ulonglong2*>(&Bs[k * 128 + tx * 8 + 4]);
        float av[8] = {a0.x, a0.y, a0.z, a0.w, a1.x, a1.y, a1.z, a1.w};
        unsigned long long bv[4] = {bb0.x, bb0.y, bb1.x, bb1.y};
#pragma unroll
        for (int i = 0; i < 8; i++) {
            unsigned long long a2 = pack2(av[i], av[i]);
#pragma unroll
            for (int j = 0; j < 4; j++) ffma2(acc[i][j], a2, bv[j]);
        }
    }
}

template<int KTOT, bool NORM, bool RELU>
__global__ __launch_bounds__(256)
void gemm_kernel(const float* __restrict__ A0, const float* __restrict__ A1,
                 const float* __restrict__ B,
                 const float* __restrict__ bias1, const float* __restrict__ bias2,
                 float* __restrict__ out)
{
    __shared__ float As[2][16 * 128];
    __shared__ float Bs[2][16 * 128];
    const int tid = threadIdx.x;
    const int tx = tid & 15, ty = tid >> 4;
    const int row0 = blockIdx.x * 128;
    const int mA = tid >> 2, k4 = (tid & 3) << 2;
    const int kB = tid >> 5, n4 = tid & 31;

    unsigned long long acc[8][4];
#pragma unroll
    for (int i = 0; i < 8; i++)
#pragma unroll
        for (int j = 0; j < 4; j++) acc[i][j] = 0ull;

    float4 ra0 = loadA_elem<KTOT>(A0, A1, row0 + mA, 0, k4);
    float4 ra1 = loadA_elem<KTOT>(A0, A1, row0 + mA + 64, 0, k4);
    float4 rb0 = reinterpret_cast<const float4*>(&B[(size_t)kB * 128])[n4];
    float4 rb1 = reinterpret_cast<const float4*>(&B[(size_t)(kB + 8) * 128])[n4];
    stsA(As[0], mA, k4, ra0);
    stsA(As[0], mA + 64, k4, ra1);
    reinterpret_cast<float4*>(&Bs[0][kB * 128])[n4] = rb0;
    reinterpret_cast<float4*>(&Bs[0][(kB + 8) * 128])[n4] = rb1;
    __syncthreads();

    int buf = 0;
    for (int kb = 16; kb < KTOT; kb += 16) {
        ra0 = loadA_elem<KTOT>(A0, A1, row0 + mA, kb, k4);
        ra1 = loadA_elem<KTOT>(A0, A1, row0 + mA + 64, kb, k4);
        rb0 = reinterpret_cast<const float4*>(&B[(size_t)(kb + kB) * 128])[n4];
        rb1 = reinterpret_cast<const float4*>(&B[(size_t)(kb + kB + 8) * 128])[n4];
        gemm_compute(As[buf], Bs[buf], acc, tx, ty);
        stsA(As[buf ^ 1], mA, k4, ra0);
        stsA(As[buf ^ 1], mA + 64, k4, ra1);
        reinterpret_cast<float4*>(&Bs[buf ^ 1][kB * 128])[n4] = rb0;
        reinterpret_cast<float4*>(&Bs[buf ^ 1][(kB + 8) * 128])[n4] = rb1;
        __syncthreads();
        buf ^= 1;
    }
    gemm_compute(As[buf], Bs[buf], acc, tx, ty);

    // epilogue
    float vals[8][8];
#pragma unroll
    for (int i = 0; i < 8; i++)
#pragma unroll
        for (int j = 0; j < 4; j++)
            unpack2(acc[i][j], vals[i][2 * j], vals[i][2 * j + 1]);

#pragma unroll
    for (int j = 0; j < 8; j++) {
        float b = bias1[tx * 8 + j];
#pragma unroll
        for (int i = 0; i < 8; i++) vals[i][j] += b;
    }

    float rn[8];
    if (NORM) {
        __syncthreads();
        float* ss = As[0];
        if (tid < 128) ss[tid] = 0.f;
        __syncthreads();
#pragma unroll
        for (int i = 0; i < 8; i++) {
            float p = 0.f;
#pragma unroll
            for (int j = 0; j < 8; j++) p += vals[i][j] * vals[i][j];
            atomicAdd(&ss[ty * 8 + i], p);
        }
        __syncthreads();
        if (tid < 128) {
            float s = ss[tid];
            Bs[0][tid] = 1.0f / fmaxf(sqrtf(s), 1e-12f);
        }
        __syncthreads();
#pragma unroll
        for (int i = 0; i < 8; i++) rn[i] = Bs[0][ty * 8 + i];
    }

#pragma unroll
    for (int i = 0; i < 8; i++) {
        int grow = row0 + ty * 8 + i;
        if (grow < N_NODES) {
            float o[8];
#pragma unroll
            for (int j = 0; j < 8; j++) {
                float v = vals[i][j];
                if (NORM) v = v * rn[i] + bias2[tx * 8 + j];
                if (RELU) v = fmaxf(v, 0.f);
                o[j] = v;
            }
            float4* dst = reinterpret_cast<float4*>(&out[(size_t)grow * 128 + tx * 8]);
            dst[0] = make_float4(o[0], o[1], o[2], o[3]);
            dst[1] = make_float4(o[4], o[5], o[6], o[7]);
        }
    }
}

// ---------------- warp-per-node aggregate (shfl broadcast + sw pipeline) --------
// agg[n] = mean_e relu(nodeproj[src(e)] + ea(e) @ We)
__global__ __launch_bounds__(128)
void agg_kernel(const float* __restrict__ nodeproj,
                const float* __restrict__ We,   // [16][128] row-major
                float* __restrict__ agg)
{
    const int lane = threadIdx.x & 31;
    const int warp = threadIdx.x >> 5;

    // each lane owns output channels [4*lane, 4*lane+4)
    ulonglong2 w[16];
#pragma unroll
    for (int k = 0; k < 16; k++)
        w[k] = reinterpret_cast<const ulonglong2*>(We)[k * 32 + lane];

    const int n = blockIdx.x * 4 + warp;
    if (n >= N_NODES) return;
    const int beg = g_off[n];
    const int cnt = g_cnt[n];
    const float4* np4 = reinterpret_cast<const float4*>(nodeproj);

    float s0 = 0.f, s1 = 0.f, s2 = 0.f, s3 = 0.f;

    for (int c = 0; c < cnt; c += 32) {
        const int nc = min(32, cnt - c);
        // one coalesced load fetches up to 32 src ids for this chunk
        int srcs = (c + lane < cnt) ? g_src_sorted[beg + c + lane] : 0;
        const int npairs = nc >> 1;

        // ---- prologue: issue pair-0 loads ----
        float eav = 0.f;
        float4 a4 = make_float4(0.f, 0.f, 0.f, 0.f);
        float4 b4 = a4;
        if (npairs > 0) {
            int sa = __shfl_sync(0xffffffffu, srcs, 0);
            int sb = __shfl_sync(0xffffffffu, srcs, 1);
            eav = g_ea_sorted[(size_t)(beg + c) * EDIM + lane]; // 2 edges x 16
            a4 = np4[(size_t)sa * 32 + lane];
            b4 = np4[(size_t)sb * 32 + lane];
        }

        for (int i = 0; i < npairs; i++) {
            // ---- prefetch pair i+1 while pair i computes ----
            float eav_n = 0.f;
            float4 a4n = make_float4(0.f, 0.f, 0.f, 0.f);
            float4 b4n = a4n;
            if (i + 1 < npairs) {
                int sa = __shfl_sync(0xffffffffu, srcs, 2 * i + 2);
                int sb = __shfl_sync(0xffffffffu, srcs, 2 * i + 3);
                eav_n = g_ea_sorted[(size_t)(beg + c + 2 * i + 2) * EDIM + lane];
                a4n = np4[(size_t)sa * 32 + lane];
                b4n = np4[(size_t)sb * 32 + lane];
            }

            // ---- compute pair i ----
            unsigned long long p0 = pack2(a4.x, a4.y), p1 = pack2(a4.z, a4.w);
            unsigned long long q0 = pack2(b4.x, b4.y), q1 = pack2(b4.z, b4.w);
#pragma unroll
            for (int k = 0; k < 16; k++) {
                float fa = __shfl_sync(0xffffffffu, eav, k);
                float fb = __shfl_sync(0xffffffffu, eav, k + 16);
                unsigned long long aa = pack2(fa, fa);
                unsigned long long bb = pack2(fb, fb);
                ffma2(p0, aa, w[k].x);
                ffma2(p1, aa, w[k].y);
                ffma2(q0, bb, w[k].x);
                ffma2(q1, bb, w[k].y);
            }
            float r0, r1, r2, r3, t0, t1, t2, t3;
            unpack2(p0, r0, r1); unpack2(p1, r2, r3);
            unpack2(q0, t0, t1); unpack2(q1, t2, t3);
            s0 += fmaxf(r0, 0.f) + fmaxf(t0, 0.f);
            s1 += fmaxf(r1, 0.f) + fmaxf(t1, 0.f);
            s2 += fmaxf(r2, 0.f) + fmaxf(t2, 0.f);
            s3 += fmaxf(r3, 0.f) + fmaxf(t3, 0.f);

            eav = eav_n; a4 = a4n; b4 = b4n;
        }

        if (nc & 1) {
            const int i = nc - 1;
            const int e = beg + c + i;
            const int src = __shfl_sync(0xffffffffu, srcs, i);
            float ev = (lane < 16) ? g_ea_sorted[(size_t)e * EDIM + lane] : 0.f;
            float4 x4 = np4[(size_t)src * 32 + lane];
            unsigned long long p0 = pack2(x4.x, x4.y), p1 = pack2(x4.z, x4.w);
#pragma unroll
            for (int k = 0; k < 16; k++) {
                float fa = __shfl_sync(0xffffffffu, ev, k);
                unsigned long long aa = pack2(fa, fa);
                ffma2(p0, aa, w[k].x);
                ffma2(p1, aa, w[k].y);
            }
            float r0, r1, r2, r3;
            unpack2(p0, r0, r1); unpack2(p1, r2, r3);
            s0 += fmaxf(r0, 0.f);
            s1 += fmaxf(r1, 0.f);
            s2 += fmaxf(r2, 0.f);
            s3 += fmaxf(r3, 0.f);
        }
    }

    const float sc = 1.0f / (float)(cnt > 1 ? cnt : 1);
    reinterpret_cast<float4*>(agg)[(size_t)n * 32 + lane] =
        make_float4(s0 * sc, s1 * sc, s2 * sc, s3 * sc);
}

// ---------------- launch -------------------------------------------------------
extern "C" void kernel_launch(void* const* d_in, const int* in_sizes, int n_in,
                              void* d_out, int out_size)
{
    const float* x         = (const float*)d_in[0];
    const void*  edge_idx  = d_in[1];
    const float* edge_attr = (const float*)d_in[2];
    const float* w_msg1    = (const float*)d_in[3];
    const float* b_msg1    = (const float*)d_in[4];
    const float* w_upd1    = (const float*)d_in[5];
    const float* b_upd1    = (const float*)d_in[6];
    const float* bias1     = (const float*)d_in[7];
    const float* w_msg2    = (const float*)d_in[8];
    const float* b_msg2    = (const float*)d_in[9];
    const float* w_upd2    = (const float*)d_in[10];
    const float* b_upd2    = (const float*)d_in[11];
    const float* bias2     = (const float*)d_in[12];
    float* out = (float*)d_out;

    float *np, *ag, *h;
    cudaGetSymbolAddress((void**)&np, g_nodeproj);
    cudaGetSymbolAddress((void**)&ag, g_agg);
    cudaGetSymbolAddress((void**)&h,  g_h);

    const int GEMM_BLOCKS = (N_NODES + 127) / 128;     // 782
    const int CNT_BLOCKS  = (N_EDGES + 255) / 256;
    const int AGG_BLOCKS  = (N_NODES + 3) / 4;         // 25000

    init_kernel<<<NB, 256>>>((const unsigned*)edge_idx);        // 0
    count_kernel<<<CNT_BLOCKS, 256>>>(edge_idx);                // 1
    reduce_kernel<<<NB, 256>>>();                               // 2
    gemm_kernel<128, false, false><<<GEMM_BLOCKS, 256>>>(       // 3 ← ncu profiles this
        x, nullptr, w_msg1, b_msg1, nullptr, np);
    scanp_kernel<<<1, 512>>>();                                 // 4
    expand_kernel<<<NB, 256>>>();                               // 5
    scatter_kernel<<<CNT_BLOCKS, 256>>>(edge_idx, edge_attr);   // 6

    // ---- layer 1 (nodeproj computed at launch 3) ----
    agg_kernel<<<AGG_BLOCKS, 128>>>(np, w_msg1 + 128 * 128, ag);          // 7
    gemm_kernel<256, true, true><<<GEMM_BLOCKS, 256>>>(                   // 8
        x, ag, w_upd1, b_upd1, bias1, h);

    // ---- layer 2 ----
    gemm_kernel<128, false, false><<<GEMM_BLOCKS, 256>>>(                 // 9
        h, nullptr, w_msg2, b_msg2, nullptr, np);
    agg_kernel<<<AGG_BLOCKS, 128>>>(np, w_msg2 + 128 * 128, ag);          // 10
    gemm_kernel<256, true, false><<<GEMM_BLOCKS, 256>>>(                  // 11
        h, ag, w_upd2, b_upd2, bias2, out);

    (void)in_sizes; (void)n_in; (void)out_size;
}

// round 9
// speedup vs baseline: 1.1736x; 1.1259x over previous
#include <cuda_runtime.h>
#include <cstdint>

#define N_NODES 100000
#define N_EDGES 1600000
#define CH      128
#define EDIM    16
#define NB      391      // ceil(N_NODES/256)

// ---------------- scratch (static device globals: no allocation) ----------------
__device__ float g_nodeproj[(size_t)N_NODES * CH];
__device__ float g_summed [(size_t)N_NODES * CH];
__device__ float g_h      [(size_t)N_NODES * CH];
__device__ float g_inv    [N_NODES];
__device__ int   g_cnt    [N_NODES];
__device__ int   g_off    [N_NODES];
__device__ int   g_cursor [N_NODES];
__device__ int   g_part   [512];
__device__ int   g_src_sorted[N_EDGES];
__device__ int   g_dst_sorted[N_EDGES];
__device__ float g_ea_sorted[(size_t)N_EDGES * EDIM];
__device__ int   g_is64;

// ---------------- packed f32x2 helpers (sm_103a) ----------------
static __device__ __forceinline__ unsigned long long pack2(float x, float y) {
    unsigned long long r;
    asm("mov.b64 %0, {%1, %2};" : "=l"(r) : "f"(x), "f"(y));
    return r;
}
static __device__ __forceinline__ void unpack2(unsigned long long v, float &x, float &y) {
    asm("mov.b64 {%0, %1}, %2;" : "=f"(x), "=f"(y) : "l"(v));
}
static __device__ __forceinline__ void ffma2(unsigned long long &d,
                                             unsigned long long a,
                                             unsigned long long b) {
    asm("fma.rn.f32x2 %0, %1, %2, %0;" : "+l"(d) : "l"(a), "l"(b));
}

// ---------------- init: zero counts + dtype sniff (int32 vs int64) -------------
__global__ void init_kernel(const unsigned* __restrict__ p) {
    int i = blockIdx.x * 256 + threadIdx.x;
    if (i < N_NODES) g_cnt[i] = 0;
    if (blockIdx.x == 0) {
        __shared__ int nz;
        if (threadIdx.x == 0) nz = 0;
        __syncthreads();
        if (p[threadIdx.x * 2 + 1] != 0u) atomicAdd(&nz, 1);
        __syncthreads();
        if (threadIdx.x == 0) g_is64 = (nz == 0) ? 1 : 0;
    }
}

static __device__ __forceinline__ int load_eidx(const void* eidx, long long i, int is64) {
    return is64 ? (int)((const long long*)eidx)[i] : ((const int*)eidx)[i];
}

__global__ void count_kernel(const void* __restrict__ eidx) {
    long long t = (long long)blockIdx.x * blockDim.x + threadIdx.x;
    if (t >= N_EDGES) return;
    int dst = load_eidx(eidx, (long long)N_EDGES + t, g_is64);
    atomicAdd(&g_cnt[dst], 1);
}

// ---------------- parallel 3-phase exclusive scan of g_cnt ----------------------
__global__ __launch_bounds__(256) void reduce_kernel() {
    int i = blockIdx.x * 256 + threadIdx.x;
    int x = (i < N_NODES) ? g_cnt[i] : 0;
    __shared__ int ws[8];
    int lane = threadIdx.x & 31, wid = threadIdx.x >> 5;
#pragma unroll
    for (int o = 16; o; o >>= 1) x += __shfl_down_sync(0xffffffffu, x, o);
    if (lane == 0) ws[wid] = x;
    __syncthreads();
    if (wid == 0) {
        int v = (lane < 8) ? ws[lane] : 0;
#pragma unroll
        for (int o = 4; o; o >>= 1) v += __shfl_down_sync(0xffffffffu, v, o);
        if (lane == 0) g_part[blockIdx.x] = v;
    }
}

__global__ __launch_bounds__(512) void scanp_kernel() {
    int tid = threadIdx.x, lane = tid & 31, wid = tid >> 5;
    int v = (tid < NB) ? g_part[tid] : 0;
    int x = v;
#pragma unroll
    for (int o = 1; o < 32; o <<= 1) {
        int y = __shfl_up_sync(0xffffffffu, x, o);
        if (lane >= o) x += y;
    }
    __shared__ int ws[16];
    if (lane == 31) ws[wid] = x;
    __syncthreads();
    if (wid == 0) {
        int t = (lane < 16) ? ws[lane] : 0;
#pragma unroll
        for (int o = 1; o < 16; o <<= 1) {
            int y = __shfl_up_sync(0xffffffffu, t, o);
            if (lane >= o) t += y;
        }
        if (lane < 16) ws[lane] = t;
    }
    __syncthreads();
    int pre = wid ? ws[wid - 1] : 0;
    if (tid < NB) g_part[tid] = pre + x - v;   // exclusive
}

__global__ __launch_bounds__(256) void expand_kernel() {
    int i = blockIdx.x * 256 + threadIdx.x;
    int v = (i < N_NODES) ? g_cnt[i] : 0;
    int lane = threadIdx.x & 31, wid = threadIdx.x >> 5;
    int x = v;
#pragma unroll
    for (int o = 1; o < 32; o <<= 1) {
        int y = __shfl_up_sync(0xffffffffu, x, o);
        if (lane >= o) x += y;
    }
    __shared__ int ws[8];
    if (lane == 31) ws[wid] = x;
    __syncthreads();
    if (wid == 0) {
        int t = (lane < 8) ? ws[lane] : 0;
#pragma unroll
        for (int o = 1; o < 8; o <<= 1) {
            int y = __shfl_up_sync(0xffffffffu, t, o);
            if (lane >= o) t += y;
        }
        if (lane < 8) ws[lane] = t;
    }
    __syncthreads();
    int excl = (wid ? ws[wid - 1] : 0) + x - v + g_part[blockIdx.x];
    if (i < N_NODES) {
        g_off[i] = excl;
        g_cursor[i] = excl;
        g_inv[i] = 1.0f / (float)(v > 1 ? v : 1);
    }
}

// scatter edges into dst-sorted order (src, dst, edge_attr payload)
__global__ void scatter_kernel(const void* __restrict__ eidx,
                               const float* __restrict__ edge_attr) {
    long long t = (long long)blockIdx.x * blockDim.x + threadIdx.x;
    if (t >= N_EDGES) return;
    const int is64 = g_is64;
    int src = load_eidx(eidx, t, is64);
    int dst = load_eidx(eidx, (long long)N_EDGES + t, is64);
    int pos = atomicAdd(&g_cursor[dst], 1);
    g_src_sorted[pos] = src;
    g_dst_sorted[pos] = dst;
    const float4* s = reinterpret_cast<const float4*>(&edge_attr[t * EDIM]);
    float4* d = reinterpret_cast<float4*>(&g_ea_sorted[(size_t)pos * EDIM]);
    d[0] = s[0]; d[1] = s[1]; d[2] = s[2]; d[3] = s[3];
}

__global__ void zero_summed_kernel() {
    size_t i = (size_t)blockIdx.x * 256 + threadIdx.x;
    if (i < (size_t)N_NODES * (CH / 4))
        reinterpret_cast<float4*>(g_summed)[i] = make_float4(0.f, 0.f, 0.f, 0.f);
}

// ---------------- double-buffered tiled GEMM ------------------------------------
// C[N,128] = [A0 | A1*inv[row]] @ B[KTOT,128] (+epilogue). BM=BN=128, BK=16, 256thr.
template<int KTOT>
static __device__ __forceinline__ float4 loadA_elem(const float* __restrict__ A0,
                                                    const float* __restrict__ A1,
                                                    const float* __restrict__ inv,
                                                    int grow, int kb, int k4) {
    float4 v = make_float4(0.f, 0.f, 0.f, 0.f);
    if (grow < N_NODES) {
        if (KTOT == 128 || kb < 128) {
            v = *reinterpret_cast<const float4*>(&A0[(size_t)grow * 128 + kb + k4]);
        } else {
            v = *reinterpret_cast<const float4*>(&A1[(size_t)grow * 128 + (kb - 128) + k4]);
            float s = inv[grow];
            v.x *= s; v.y *= s; v.z *= s; v.w *= s;
        }
    }
    return v;
}

static __device__ __forceinline__ void stsA(float* As, int m, int k4, float4 v) {
    As[(k4 + 0) * 128 + m] = v.x;
    As[(k4 + 1) * 128 + m] = v.y;
    As[(k4 + 2) * 128 + m] = v.z;
    As[(k4 + 3) * 128 + m] = v.w;
}

static __device__ __forceinline__ void gemm_compute(const float* __restrict__ As,
                                                    const float* __restrict__ Bs,
                                                    unsigned long long acc[8][4],
                                                    int tx, int ty) {
#pragma unroll
    for (int k = 0; k < 16; k++) {
        float4 a0 = *reinterpret_cast<const float4*>(&As[k * 128 + ty * 8]);
        float4 a1 = *reinterpret_cast<const float4*>(&As[k * 128 + ty * 8 + 4]);
        ulonglong2 bb0 = *reinterpret_cast<const ulonglong2*>(&Bs[k * 128 + tx * 8]);
        ulonglong2 bb1 = *reinterpret_cast<const ulonglong2*>(&Bs[k * 128 + tx * 8 + 4]);
        float av[8] = {a0.x, a0.y, a0.z, a0.w, a1.x, a1.y, a1.z, a1.w};
        unsigned long long bv[4] = {bb0.x, bb0.y, bb1.x, bb1.y};
#pragma unroll
        for (int i = 0; i < 8; i++) {
            unsigned long long a2 = pack2(av[i], av[i]);
#pragma unroll
            for (int j = 0; j < 4; j++) ffma2(acc[i][j], a2, bv[j]);
        }
    }
}

template<int KTOT, bool NORM, bool RELU>
__global__ __launch_bounds__(256)
void gemm_kernel(const float* __restrict__ A0, const float* __restrict__ A1,
                 const float* __restrict__ inv,
                 const float* __restrict__ B,
                 const float* __restrict__ bias1, const float* __restrict__ bias2,
                 float* __restrict__ out)
{
    __shared__ float As[2][16 * 128];
    __shared__ float Bs[2][16 * 128];
    const int tid = threadIdx.x;
    const int tx = tid & 15, ty = tid >> 4;
    const int row0 = blockIdx.x * 128;
    const int mA = tid >> 2, k4 = (tid & 3) << 2;
    const int kB = tid >> 5, n4 = tid & 31;

    unsigned long long acc[8][4];
#pragma unroll
    for (int i = 0; i < 8; i++)
#pragma unroll
        for (int j = 0; j < 4; j++) acc[i][j] = 0ull;

    float4 ra0 = loadA_elem<KTOT>(A0, A1, inv, row0 + mA, 0, k4);
    float4 ra1 = loadA_elem<KTOT>(A0, A1, inv, row0 + mA + 64, 0, k4);
    float4 rb0 = reinterpret_cast<const float4*>(&B[(size_t)kB * 128])[n4];
    float4 rb1 = reinterpret_cast<const float4*>(&B[(size_t)(kB + 8) * 128])[n4];
    stsA(As[0], mA, k4, ra0);
    stsA(As[0], mA + 64, k4, ra1);
    reinterpret_cast<float4*>(&Bs[0][kB * 128])[n4] = rb0;
    reinterpret_cast<float4*>(&Bs[0][(kB + 8) * 128])[n4] = rb1;
    __syncthreads();

    int buf = 0;
    for (int kb = 16; kb < KTOT; kb += 16) {
        ra0 = loadA_elem<KTOT>(A0, A1, inv, row0 + mA, kb, k4);
        ra1 = loadA_elem<KTOT>(A0, A1, inv, row0 + mA + 64, kb, k4);
        rb0 = reinterpret_cast<const float4*>(&B[(size_t)(kb + kB) * 128])[n4];
        rb1 = reinterpret_cast<const float4*>(&B[(size_t)(kb + kB + 8) * 128])[n4];
        gemm_compute(As[buf], Bs[buf], acc, tx, ty);
        stsA(As[buf ^ 1], mA, k4, ra0);
        stsA(As[buf ^ 1], mA + 64, k4, ra1);
        reinterpret_cast<float4*>(&Bs[buf ^ 1][kB * 128])[n4] = rb0;
        reinterpret_cast<float4*>(&Bs[buf ^ 1][(kB + 8) * 128])[n4] = rb1;
        __syncthreads();
        buf ^= 1;
    }
    gemm_compute(As[buf], Bs[buf], acc, tx, ty);

    // epilogue
    float vals[8][8];
#pragma unroll
    for (int i = 0; i < 8; i++)
#pragma unroll
        for (int j = 0; j < 4; j++)
            unpack2(acc[i][j], vals[i][2 * j], vals[i][2 * j + 1]);

#pragma unroll
    for (int j = 0; j < 8; j++) {
        float b = bias1[tx * 8 + j];
#pragma unroll
        for (int i = 0; i < 8; i++) vals[i][j] += b;
    }

    float rn[8];
    if (NORM) {
        __syncthreads();
        float* ss = As[0];
        if (tid < 128) ss[tid] = 0.f;
        __syncthreads();
#pragma unroll
        for (int i = 0; i < 8; i++) {
            float p = 0.f;
#pragma unroll
            for (int j = 0; j < 8; j++) p += vals[i][j] * vals[i][j];
            atomicAdd(&ss[ty * 8 + i], p);
        }
        __syncthreads();
        if (tid < 128) {
            float s = ss[tid];
            Bs[0][tid] = 1.0f / fmaxf(sqrtf(s), 1e-12f);
        }
        __syncthreads();
#pragma unroll
        for (int i = 0; i < 8; i++) rn[i] = Bs[0][ty * 8 + i];
    }

#pragma unroll
    for (int i = 0; i < 8; i++) {
        int grow = row0 + ty * 8 + i;
        if (grow < N_NODES) {
            float o[8];
#pragma unroll
            for (int j = 0; j < 8; j++) {
                float v = vals[i][j];
                if (NORM) v = v * rn[i] + bias2[tx * 8 + j];
                if (RELU) v = fmaxf(v, 0.f);
                o[j] = v;
            }
            float4* dst = reinterpret_cast<float4*>(&out[(size_t)grow * 128 + tx * 8]);
            dst[0] = make_float4(o[0], o[1], o[2], o[3]);
            dst[1] = make_float4(o[4], o[5], o[6], o[7]);
        }
    }
}

// ---------------- edge-parallel message kernel (balanced: 32 edges/warp) --------
// summed[dst] += relu(nodeproj[src] + ea @ We); runs of equal dst flushed with
// one red.global.add.v4 per lane. N_EDGES == 32 * 50000 exactly.
__global__ __launch_bounds__(128)
void edgemsg_kernel(const float* __restrict__ nodeproj,
                    const float* __restrict__ We,   // [16][128] row-major fp32
                    float* __restrict__ summed)
{
    const int lane = threadIdx.x & 31;
    const int warp = threadIdx.x >> 5;

    // lane owns output channels [4*lane, 4*lane+4)
    ulonglong2 w[16];
#pragma unroll
    for (int k = 0; k < 16; k++)
        w[k] = reinterpret_cast<const ulonglong2*>(We)[k * 32 + lane];

    const long long e0 = ((long long)blockIdx.x * 4 + warp) * 32;
    if (e0 >= N_EDGES) return;
    const float4* np4 = reinterpret_cast<const float4*>(nodeproj);

    // preload this warp's 32 src/dst ids (coalesced)
    const int srcs = g_src_sorted[e0 + lane];
    const int dsts = g_dst_sorted[e0 + lane];

    int i = 0;
    while (i < 32) {
        const int dst = __shfl_sync(0xffffffffu, dsts, i);
        unsigned neq = __ballot_sync(0xffffffffu, dsts != dst) & (0xffffffffu << i);
        const int j = neq ? (__ffs(neq) - 1) : 32;   // run = [i, j)

        float s0 = 0.f, s1 = 0.f, s2 = 0.f, s3 = 0.f;

        int k = i;
        for (; k + 2 <= j; k += 2) {
            const long long e = e0 + k;
            const int src0 = __shfl_sync(0xffffffffu, srcs, k);
            const int src1 = __shfl_sync(0xffffffffu, srcs, k + 1);
            float eav = g_ea_sorted[e * EDIM + lane];   // 2 edges x 16 attrs, 128B

            float4 a4 = np4[(size_t)src0 * 32 + lane];
            float4 b4 = np4[(size_t)src1 * 32 + lane];
            unsigned long long p0 = pack2(a4.x, a4.y), p1 = pack2(a4.z, a4.w);
            unsigned long long q0 = pack2(b4.x, b4.y), q1 = pack2(b4.z, b4.w);
#pragma unroll
            for (int kk = 0; kk < 16; kk++) {
                float fa = __shfl_sync(0xffffffffu, eav, kk);
                float fb = __shfl_sync(0xffffffffu, eav, kk + 16);
                unsigned long long aa = pack2(fa, fa);
                unsigned long long bb = pack2(fb, fb);
                ffma2(p0, aa, w[kk].x);
                ffma2(p1, aa, w[kk].y);
                ffma2(q0, bb, w[kk].x);
                ffma2(q1, bb, w[kk].y);
            }
            float r0, r1, r2, r3, t0, t1, t2, t3;
            unpack2(p0, r0, r1); unpack2(p1, r2, r3);
            unpack2(q0, t0, t1); unpack2(q1, t2, t3);
            s0 += fmaxf(r0, 0.f) + fmaxf(t0, 0.f);
            s1 += fmaxf(r1, 0.f) + fmaxf(t1, 0.f);
            s2 += fmaxf(r2, 0.f) + fmaxf(t2, 0.f);
            s3 += fmaxf(r3, 0.f) + fmaxf(t3, 0.f);
        }
        if (k < j) {
            const long long e = e0 + k;
            const int src = __shfl_sync(0xffffffffu, srcs, k);
            float eav = (lane < 16) ? g_ea_sorted[e * EDIM + lane] : 0.f;
            float4 a4 = np4[(size_t)src * 32 + lane];
            unsigned long long p0 = pack2(a4.x, a4.y), p1 = pack2(a4.z, a4.w);
#pragma unroll
            for (int kk = 0; kk < 16; kk++) {
                float fa = __shfl_sync(0xffffffffu, eav, kk);
                unsigned long long aa = pack2(fa, fa);
                ffma2(p0, aa, w[kk].x);
                ffma2(p1, aa, w[kk].y);
            }
            float r0, r1, r2, r3;
            unpack2(p0, r0, r1); unpack2(p1, r2, r3);
            s0 += fmaxf(r0, 0.f);
            s1 += fmaxf(r1, 0.f);
            s2 += fmaxf(r2, 0.f);
            s3 += fmaxf(r3, 0.f);
        }

        float* p = &summed[(size_t)dst * 128 + lane * 4];
        asm volatile("red.global.add.v4.f32 [%0], {%1,%2,%3,%4};"
                     :: "l"(p), "f"(s0), "f"(s1), "f"(s2), "f"(s3) : "memory");
        i = j;
    }
}

// ---------------- launch -------------------------------------------------------
extern "C" void kernel_launch(void* const* d_in, const int* in_sizes, int n_in,
                              void* d_out, int out_size)
{
    const float* x         = (const float*)d_in[0];
    const void*  edge_idx  = d_in[1];
    const float* edge_attr = (const float*)d_in[2];
    const float* w_msg1    = (const float*)d_in[3];
    const float* b_msg1    = (const float*)d_in[4];
    const float* w_upd1    = (const float*)d_in[5];
    const float* b_upd1    = (const float*)d_in[6];
    const float* bias1     = (const float*)d_in[7];
    const float* w_msg2    = (const float*)d_in[8];
    const float* b_msg2    = (const float*)d_in[9];
    const float* w_upd2    = (const float*)d_in[10];
    const float* b_upd2    = (const float*)d_in[11];
    const float* bias2     = (const float*)d_in[12];
    float* out = (float*)d_out;

    float *np, *sm, *h, *inv;
    cudaGetSymbolAddress((void**)&np,  g_nodeproj);
    cudaGetSymbolAddress((void**)&sm,  g_summed);
    cudaGetSymbolAddress((void**)&h,   g_h);
    cudaGetSymbolAddress((void**)&inv, g_inv);

    const int GEMM_BLOCKS = (N_NODES + 127) / 128;       // 782
    const int CNT_BLOCKS  = (N_EDGES + 255) / 256;
    const int ZS_BLOCKS   = (N_NODES * (CH / 4) + 255) / 256;
    const int EM_BLOCKS   = N_EDGES / 128;               // 12500 (4 warps/block)

    init_kernel<<<NB, 256>>>((const unsigned*)edge_idx);                 // 0
    count_kernel<<<CNT_BLOCKS, 256>>>(edge_idx);                         // 1
    reduce_kernel<<<NB, 256>>>();                                        // 2
    gemm_kernel<128, false, false><<<GEMM_BLOCKS, 256>>>(                // 3 ← profiled
        x, nullptr, nullptr, w_msg1, b_msg1, nullptr, np);
    scanp_kernel<<<1, 512>>>();                                          // 4
    expand_kernel<<<NB, 256>>>();                                        // 5
    scatter_kernel<<<CNT_BLOCKS, 256>>>(edge_idx, edge_attr);            // 6

    // ---- layer 1 (nodeproj computed at launch 3) ----
    zero_summed_kernel<<<ZS_BLOCKS, 256>>>();                            // 7
    edgemsg_kernel<<<EM_BLOCKS, 128>>>(np, w_msg1 + 128 * 128, sm);      // 8
    gemm_kernel<256, true, true><<<GEMM_BLOCKS, 256>>>(                  // 9
        x, sm, inv, w_upd1, b_upd1, bias1, h);

    // ---- layer 2 ----
    gemm_kernel<128, false, false><<<GEMM_BLOCKS, 256>>>(                // 10
        h, nullptr, nullptr, w_msg2, b_msg2, nullptr, np);
    zero_summed_kernel<<<ZS_BLOCKS, 256>>>();                            // 11
    edgemsg_kernel<<<EM_BLOCKS, 128>>>(np, w_msg2 + 128 * 128, sm);      // 12
    gemm_kernel<256, true, false><<<GEMM_BLOCKS, 256>>>(                 // 13
        h, sm, inv, w_upd2, b_upd2, bias2, out);

    (void)in_sizes; (void)n_in; (void)out_size;
}